// round 2
// baseline (speedup 1.0000x reference)
#include <cuda_runtime.h>
#include <math.h>

// Problem constants
#define B_IMG   32
#define HW      56
#define CCH     192
#define NHEAD   6
#define HDIM    32
#define NTOK    49        // tokens per window (7x7)
#define NWIN    64        // windows per image (8x8)
#define BWIN    2048      // total windows
#define TOK     100352    // total tokens = BWIN*NTOK
#define SHIFT_  3
#define QSCALE  0.17677669529663687f   // 1/sqrt(32)

// ---------------- scratch (device globals; no allocation allowed) ----------
__device__ float g_xw [ (size_t)TOK * CCH ];           // LN'd + shifted + window-partitioned
__device__ float g_q  [ (size_t)BWIN * NHEAD * NTOK * HDIM ];
__device__ float g_k  [ (size_t)BWIN * NHEAD * NTOK * HDIM ];
__device__ float g_v  [ (size_t)BWIN * NHEAD * NTOK * HDIM ];
__device__ float g_ctx[ (size_t)TOK * CCH ];           // attention output [B_, N, C]
__device__ float g_y  [ (size_t)TOK * CCH ];           // after proj, window-reversed, in token order
__device__ float g_bias6[ NHEAD * NTOK * NTOK ];       // rel-pos bias gathered per head

// ---------------- K0: gather relative-position bias ------------------------
__global__ void bias_kernel(const float* __restrict__ table, const int* __restrict__ idx)
{
    int i = blockIdx.x * blockDim.x + threadIdx.x;
    if (i < NHEAD * NTOK * NTOK) {
        int h = i / (NTOK * NTOK);
        int e = i % (NTOK * NTOK);
        g_bias6[i] = table[idx[e] * NHEAD + h];
    }
}

// ---------------- K1: LayerNorm + cyclic shift + window partition -----------
// one warp per output token (window order); gathered read from inputs
__global__ void __launch_bounds__(256) ln_kernel(const float* __restrict__ x,
                                                 const float* __restrict__ g,
                                                 const float* __restrict__ b)
{
    int wid  = (blockIdx.x * blockDim.x + threadIdx.x) >> 5;   // token id in window order
    int lane = threadIdx.x & 31;
    if (wid >= TOK) return;

    int w  = wid / NTOK, n = wid % NTOK;
    int bb = w >> 6, wi = w & 63;
    int wh = wi >> 3, ww = wi & 7;
    int ii = n / 7,  jj = n % 7;
    int hh = (wh * 7 + ii + SHIFT_) % HW;
    int w2 = (ww * 7 + jj + SHIFT_) % HW;
    const float* src = x + ((size_t)bb * (HW * HW) + hh * HW + w2) * CCH;

    float vals[6];
    float s = 0.f, s2 = 0.f;
#pragma unroll
    for (int u = 0; u < 6; u++) {
        float v = src[lane + u * 32];
        vals[u] = v; s += v; s2 += v * v;
    }
#pragma unroll
    for (int off = 16; off; off >>= 1) {
        s  += __shfl_xor_sync(0xFFFFFFFFu, s,  off);
        s2 += __shfl_xor_sync(0xFFFFFFFFu, s2, off);
    }
    float mu  = s * (1.f / CCH);
    float var = s2 * (1.f / CCH) - mu * mu;
    float inv = rsqrtf(var + 1e-5f);

    float* dst = g_xw + (size_t)wid * CCH;
#pragma unroll
    for (int u = 0; u < 6; u++) {
        int c = lane + u * 32;
        dst[c] = (vals[u] - mu) * inv * g[c] + b[c];
    }
}

// ---------------- tiled fp32 GEMM: out = A[M,192] @ W[N,192]^T + epilogue ----
// BM=128, BN=64, BK=16, 256 threads, 8x4 micro-tile per thread
// EPI: 0 = qkv scatter (A=g_xw), 1 = proj + window-reverse scatter (A=g_ctx),
//      2 = lin + GELU + residual -> d_out (A=g_y)
template<int EPI>
__global__ void __launch_bounds__(256) gemm_kernel(const float* __restrict__ W,
                                                   const float* __restrict__ bias,
                                                   const float* __restrict__ resid,
                                                   float* __restrict__ out)
{
    const float* A = (EPI == 0) ? g_xw : (EPI == 1 ? g_ctx : g_y);

    __shared__ float As[16][132];
    __shared__ float Bs[16][68];

    int tid = threadIdx.x;
    int tx = tid & 15, ty = tid >> 4;
    int row0 = blockIdx.x * 128;
    int col0 = blockIdx.y * 64;

    float acc[8][4];
#pragma unroll
    for (int i = 0; i < 8; i++)
#pragma unroll
        for (int j = 0; j < 4; j++) acc[i][j] = 0.f;

    for (int k0 = 0; k0 < CCH; k0 += 16) {
        // load A tile 128x16 (512 float4, 2 per thread)
#pragma unroll
        for (int i = 0; i < 2; i++) {
            int f = tid + i * 256;
            int r = f >> 2, kk = (f & 3) << 2;
            float4 a4 = *(const float4*)(A + (size_t)(row0 + r) * CCH + k0 + kk);
            As[kk + 0][r] = a4.x; As[kk + 1][r] = a4.y;
            As[kk + 2][r] = a4.z; As[kk + 3][r] = a4.w;
        }
        // load W tile 64x16 (256 float4, 1 per thread)
        {
            int r = tid >> 2, kk = (tid & 3) << 2;
            float4 b4 = *(const float4*)(W + (size_t)(col0 + r) * CCH + k0 + kk);
            Bs[kk + 0][r] = b4.x; Bs[kk + 1][r] = b4.y;
            Bs[kk + 2][r] = b4.z; Bs[kk + 3][r] = b4.w;
        }
        __syncthreads();

#pragma unroll
        for (int kk = 0; kk < 16; kk++) {
            float4 a0 = *(const float4*)&As[kk][ty * 8];
            float4 a1 = *(const float4*)&As[kk][ty * 8 + 4];
            float4 bb = *(const float4*)&Bs[kk][tx * 4];
            float a[8] = {a0.x, a0.y, a0.z, a0.w, a1.x, a1.y, a1.z, a1.w};
            float bv[4] = {bb.x, bb.y, bb.z, bb.w};
#pragma unroll
            for (int i = 0; i < 8; i++)
#pragma unroll
                for (int j = 0; j < 4; j++) acc[i][j] += a[i] * bv[j];
        }
        __syncthreads();
    }

    // ------------- epilogues -------------
#pragma unroll
    for (int i2 = 0; i2 < 8; i2++) {
        int r = row0 + ty * 8 + i2;
        if (EPI == 0) {
            int w = r / NTOK, n = r % NTOK;
#pragma unroll
            for (int j2 = 0; j2 < 4; j2++) {
                int o = col0 + tx * 4 + j2;
                float val = acc[i2][j2] + bias[o];
                int m = o / CCH, rem = o % CCH;
                int h = rem >> 5, d = rem & 31;
                size_t idx = (((size_t)(w * NHEAD + h)) * NTOK + n) * HDIM + d;
                if (m == 0)      g_q[idx] = val * QSCALE;
                else if (m == 1) g_k[idx] = val;
                else             g_v[idx] = val;
            }
        } else if (EPI == 1) {
            int w = r / NTOK, n = r % NTOK;
            int bb = w >> 6, wi = w & 63;
            int wh = wi >> 3, ww = wi & 7;
            int ii = n / 7, jj = n % 7;
            int hh = (wh * 7 + ii + SHIFT_) % HW;
            int w2 = (ww * 7 + jj + SHIFT_) % HW;
            float* dst = g_y + ((size_t)bb * (HW * HW) + hh * HW + w2) * CCH;
#pragma unroll
            for (int j2 = 0; j2 < 4; j2++) {
                int c = col0 + tx * 4 + j2;
                dst[c] = acc[i2][j2] + bias[c];
            }
        } else {
            const float* rs = resid + (size_t)r * CCH;
            float* dp = out + (size_t)r * CCH;
#pragma unroll
            for (int j2 = 0; j2 < 4; j2++) {
                int c = col0 + tx * 4 + j2;
                float v = acc[i2][j2] + bias[c];
                float ge = 0.5f * v * (1.f + erff(v * 0.70710678118654752f));
                dp[c] = rs[c] + ge;
            }
        }
    }
}

// ---------------- K3: windowed attention, one CTA per (window, head) --------
__global__ void __launch_bounds__(256) attn_kernel(const float* __restrict__ mask)
{
    __shared__ float qs[NTOK * HDIM];   // 49*32
    __shared__ float ks[NTOK * HDIM];
    __shared__ float vs[NTOK * HDIM];
    __shared__ float ss[NTOK * NTOK];   // 49*49

    int w = blockIdx.x;
    int h = blockIdx.y;
    int tid = threadIdx.x;

    size_t base = ((size_t)(w * NHEAD + h)) * NTOK * HDIM;
    // cooperative load q,k,v (1568 floats each = 392 float4 each)
    for (int f = tid; f < 392; f += 256) {
        ((float4*)qs)[f] = ((const float4*)(g_q + base))[f];
        ((float4*)ks)[f] = ((const float4*)(g_k + base))[f];
        ((float4*)vs)[f] = ((const float4*)(g_v + base))[f];
    }
    __syncthreads();

    int wi = w & 63;
    const float* bia = g_bias6 + h * (NTOK * NTOK);
    const float* msk = mask + (size_t)wi * (NTOK * NTOK);

    // scores
    for (int e = tid; e < NTOK * NTOK; e += 256) {
        int n = e / NTOK, m = e % NTOK;
        float s = 0.f;
        const float* qp = qs + n * HDIM;
        const float* kp = ks + m * HDIM;
#pragma unroll
        for (int d = 0; d < HDIM; d++) s += qp[d] * kp[d];
        ss[e] = s + bia[e] + msk[e];
    }
    __syncthreads();

    // softmax: warp per row
    int wrp = tid >> 5, lane = tid & 31;
    for (int row = wrp; row < NTOK; row += 8) {
        float x0 = ss[row * NTOK + lane];
        float x1 = (lane + 32 < NTOK) ? ss[row * NTOK + lane + 32] : -1e30f;
        float mx = fmaxf(x0, x1);
#pragma unroll
        for (int off = 16; off; off >>= 1)
            mx = fmaxf(mx, __shfl_xor_sync(0xFFFFFFFFu, mx, off));
        float e0 = __expf(x0 - mx);
        float e1 = (lane + 32 < NTOK) ? __expf(x1 - mx) : 0.f;
        float sum = e0 + e1;
#pragma unroll
        for (int off = 16; off; off >>= 1)
            sum += __shfl_xor_sync(0xFFFFFFFFu, sum, off);
        float inv = 1.f / sum;
        ss[row * NTOK + lane] = e0 * inv;
        if (lane + 32 < NTOK) ss[row * NTOK + lane + 32] = e1 * inv;
    }
    __syncthreads();

    // ctx = probs @ v  -> g_ctx[B_, N, C] with head as channel slice
    float* op = g_ctx + (size_t)w * NTOK * CCH + h * HDIM;
    for (int e = tid; e < NTOK * HDIM; e += 256) {
        int n = e >> 5, d = e & 31;
        float s = 0.f;
        const float* pr = ss + n * NTOK;
#pragma unroll
        for (int m = 0; m < NTOK; m++) s += pr[m] * vs[m * HDIM + d];
        op[n * CCH + d] = s;
    }
}

// ---------------- launch ----------------------------------------------------
extern "C" void kernel_launch(void* const* d_in, const int* in_sizes, int n_in,
                              void* d_out, int out_size)
{
    const float* inputs = (const float*)d_in[0];
    const float* amask  = (const float*)d_in[1];
    const float* n1g    = (const float*)d_in[2];
    const float* n1b    = (const float*)d_in[3];
    const float* qkvw   = (const float*)d_in[4];
    const float* qkvb   = (const float*)d_in[5];
    const float* rpt    = (const float*)d_in[6];
    const int*   rpi    = (const int*)d_in[7];
    const float* pw     = (const float*)d_in[8];
    const float* pb     = (const float*)d_in[9];
    const float* lw     = (const float*)d_in[10];
    const float* lb     = (const float*)d_in[11];
    float* out = (float*)d_out;

    bias_kernel<<<(NHEAD * NTOK * NTOK + 255) / 256, 256>>>(rpt, rpi);
    ln_kernel<<<TOK / 8, 256>>>(inputs, n1g, n1b);
    gemm_kernel<0><<<dim3(TOK / 128, 9), 256>>>(qkvw, qkvb, nullptr, nullptr);
    attn_kernel<<<dim3(BWIN, NHEAD), 256>>>(amask);
    gemm_kernel<1><<<dim3(TOK / 128, 3), 256>>>(pw, pb, nullptr, nullptr);
    gemm_kernel<2><<<dim3(TOK / 128, 3), 256>>>(lw, lb, inputs, out);
}

// round 3
// speedup vs baseline: 4.9491x; 4.9491x over previous
#include <cuda_runtime.h>
#include <math.h>

// Problem constants
#define B_IMG   32
#define HW      56
#define CCH     192
#define NHEAD   6
#define HDIM    32
#define NTOK    49
#define NWIN    64
#define BWIN    2048
#define TOK     100352
#define SHIFT_  3
#define QSCALE  0.17677669529663687f

// ---------------- scratch ----------------
__device__ float g_xw [ (size_t)TOK * CCH ];
__device__ float g_q  [ (size_t)BWIN * NHEAD * NTOK * HDIM ];
__device__ float g_k  [ (size_t)BWIN * NHEAD * NTOK * HDIM ];
__device__ float g_v  [ (size_t)BWIN * NHEAD * NTOK * HDIM ];
__device__ float g_ctx[ (size_t)TOK * CCH ];
__device__ float g_y  [ (size_t)TOK * CCH ];
__device__ float g_bias6[ NHEAD * NTOK * NTOK ];

// ---------------- K0: rel-pos bias gather ----------------
__global__ void bias_kernel(const float* __restrict__ table, const int* __restrict__ idx)
{
    int i = blockIdx.x * blockDim.x + threadIdx.x;
    if (i < NHEAD * NTOK * NTOK) {
        int h = i / (NTOK * NTOK);
        int e = i % (NTOK * NTOK);
        g_bias6[i] = table[idx[e] * NHEAD + h];
    }
}

// ---------------- K1: LN + shift + window partition ----------------
__global__ void __launch_bounds__(256) ln_kernel(const float* __restrict__ x,
                                                 const float* __restrict__ g,
                                                 const float* __restrict__ b)
{
    int wid  = (blockIdx.x * blockDim.x + threadIdx.x) >> 5;
    int lane = threadIdx.x & 31;
    if (wid >= TOK) return;

    int w  = wid / NTOK, n = wid % NTOK;
    int bb = w >> 6, wi = w & 63;
    int wh = wi >> 3, ww = wi & 7;
    int ii = n / 7,  jj = n % 7;
    int hh = (wh * 7 + ii + SHIFT_) % HW;
    int w2 = (ww * 7 + jj + SHIFT_) % HW;
    const float* src = x + ((size_t)bb * (HW * HW) + hh * HW + w2) * CCH;

    float vals[6];
    float s = 0.f, s2 = 0.f;
#pragma unroll
    for (int u = 0; u < 6; u++) {
        float v = src[lane + u * 32];
        vals[u] = v; s += v; s2 += v * v;
    }
#pragma unroll
    for (int off = 16; off; off >>= 1) {
        s  += __shfl_xor_sync(0xFFFFFFFFu, s,  off);
        s2 += __shfl_xor_sync(0xFFFFFFFFu, s2, off);
    }
    float mu  = s * (1.f / CCH);
    float var = s2 * (1.f / CCH) - mu * mu;
    float inv = rsqrtf(var + 1e-5f);

    float* dst = g_xw + (size_t)wid * CCH;
#pragma unroll
    for (int u = 0; u < 6; u++) {
        int c = lane + u * 32;
        dst[c] = (vals[u] - mu) * inv * g[c] + b[c];
    }
}

// ---------------- tf32 helpers ----------------
__device__ __forceinline__ float to_tf32(float x) {
    unsigned u;
    asm("cvt.rna.tf32.f32 %0, %1;" : "=r"(u) : "f"(x));
    return __uint_as_float(u);
}

__device__ __forceinline__ void mma_tf32(float* d, const unsigned* a, const unsigned* b) {
    asm volatile(
        "mma.sync.aligned.m16n8k8.row.col.f32.tf32.tf32.f32 "
        "{%0,%1,%2,%3}, {%4,%5,%6,%7}, {%8,%9}, {%0,%1,%2,%3};\n"
        : "+f"(d[0]), "+f"(d[1]), "+f"(d[2]), "+f"(d[3])
        : "r"(a[0]), "r"(a[1]), "r"(a[2]), "r"(a[3]), "r"(b[0]), "r"(b[1]));
}

// ---------------- tf32 MMA GEMM: out = A[M,192] @ W[N,192]^T + epilogue -----
// BM=128, BN=64, BK=32, 256 threads (8 warps, 4x2), warp tile 32x32
template<int EPI>
__global__ void __launch_bounds__(256) gemm_kernel(const float* __restrict__ W,
                                                   const float* __restrict__ bias,
                                                   const float* __restrict__ resid,
                                                   float* __restrict__ out)
{
    const float* A = (EPI == 0) ? g_xw : (EPI == 1 ? g_ctx : g_y);

    __shared__ __align__(16) float As[128 * 36];
    __shared__ __align__(16) float Bs[64 * 36];

    int tid  = threadIdx.x;
    int lane = tid & 31, wid = tid >> 5;
    int wm = wid >> 1, wn = wid & 1;
    int gid = lane >> 2, qid = lane & 3;
    int row0 = blockIdx.x * 128;
    int col0 = blockIdx.y * 64;

    float acc[2][4][4];
#pragma unroll
    for (int i = 0; i < 2; i++)
#pragma unroll
        for (int j = 0; j < 4; j++)
#pragma unroll
            for (int r = 0; r < 4; r++) acc[i][j][r] = 0.f;

    for (int k0 = 0; k0 < CCH; k0 += 32) {
        // A tile: 128x32 = 1024 float4, 4 per thread
#pragma unroll
        for (int i = 0; i < 4; i++) {
            int f = tid + i * 256;
            int r = f >> 3, kk = (f & 7) << 2;
            float4 v = *(const float4*)(A + (size_t)(row0 + r) * CCH + k0 + kk);
            float4 c = make_float4(to_tf32(v.x), to_tf32(v.y), to_tf32(v.z), to_tf32(v.w));
            *(float4*)&As[r * 36 + kk] = c;
        }
        // B tile: 64x32 = 512 float4, 2 per thread
#pragma unroll
        for (int i = 0; i < 2; i++) {
            int f = tid + i * 256;
            int r = f >> 3, kk = (f & 7) << 2;
            float4 v = *(const float4*)(W + (size_t)(col0 + r) * CCH + k0 + kk);
            float4 c = make_float4(to_tf32(v.x), to_tf32(v.y), to_tf32(v.z), to_tf32(v.w));
            *(float4*)&Bs[r * 36 + kk] = c;
        }
        __syncthreads();

#pragma unroll
        for (int ks = 0; ks < 32; ks += 8) {
            unsigned af[2][4], bf[4][2];
#pragma unroll
            for (int mi = 0; mi < 2; mi++) {
                int r = wm * 32 + mi * 16 + gid;
                af[mi][0] = __float_as_uint(As[r * 36 + ks + qid]);
                af[mi][1] = __float_as_uint(As[(r + 8) * 36 + ks + qid]);
                af[mi][2] = __float_as_uint(As[r * 36 + ks + qid + 4]);
                af[mi][3] = __float_as_uint(As[(r + 8) * 36 + ks + qid + 4]);
            }
#pragma unroll
            for (int ni = 0; ni < 4; ni++) {
                int n = wn * 32 + ni * 8 + gid;
                bf[ni][0] = __float_as_uint(Bs[n * 36 + ks + qid]);
                bf[ni][1] = __float_as_uint(Bs[n * 36 + ks + qid + 4]);
            }
#pragma unroll
            for (int mi = 0; mi < 2; mi++)
#pragma unroll
                for (int ni = 0; ni < 4; ni++)
                    mma_tf32(acc[mi][ni], af[mi], bf[ni]);
        }
        __syncthreads();
    }

    // ---- epilogue, per accumulator element ----
#pragma unroll
    for (int mi = 0; mi < 2; mi++) {
#pragma unroll
        for (int reg = 0; reg < 4; reg++) {
            int r = row0 + wm * 32 + mi * 16 + gid + ((reg >= 2) ? 8 : 0);
            // per-row precompute
            int w = r / NTOK, n = r % NTOK;
            if (EPI == 0) {
#pragma unroll
                for (int ni = 0; ni < 4; ni++) {
                    int o = col0 + wn * 32 + ni * 8 + qid * 2 + (reg & 1);
                    float val = acc[mi][ni][reg] + bias[o];
                    int m = o / CCH, rem = o % CCH;
                    int h = rem >> 5, d = rem & 31;
                    size_t idx = (((size_t)(w * NHEAD + h)) * NTOK + n) * HDIM + d;
                    if (m == 0)      g_q[idx] = val * QSCALE;
                    else if (m == 1) g_k[idx] = val;
                    else             g_v[idx] = val;
                }
            } else if (EPI == 1) {
                int bb = w >> 6, wi = w & 63;
                int wh = wi >> 3, ww = wi & 7;
                int ii = n / 7, jj = n % 7;
                int hh = (wh * 7 + ii + SHIFT_) % HW;
                int w2 = (ww * 7 + jj + SHIFT_) % HW;
                float* dst = g_y + ((size_t)bb * (HW * HW) + hh * HW + w2) * CCH;
#pragma unroll
                for (int ni = 0; ni < 4; ni++) {
                    int c = col0 + wn * 32 + ni * 8 + qid * 2 + (reg & 1);
                    dst[c] = acc[mi][ni][reg] + bias[c];
                }
            } else {
                const float* rs = resid + (size_t)r * CCH;
                float* dp = out + (size_t)r * CCH;
#pragma unroll
                for (int ni = 0; ni < 4; ni++) {
                    int c = col0 + wn * 32 + ni * 8 + qid * 2 + (reg & 1);
                    float v = acc[mi][ni][reg] + bias[c];
                    float ge = 0.5f * v * (1.f + erff(v * 0.70710678118654752f));
                    dp[c] = rs[c] + ge;
                }
            }
        }
    }
}

// ---------------- K3: windowed attention (conflict-free, fused softmax) -----
__global__ void __launch_bounds__(256) attn_kernel(const float* __restrict__ mask)
{
    __shared__ float qs[NTOK * HDIM];
    __shared__ float vs[NTOK * HDIM];
    __shared__ float ksT[32 * 57 + 32];     // transposed K, odd stride, padded
    __shared__ float ps[NTOK * NTOK];

    int w = blockIdx.x;
    int h = blockIdx.y;
    int tid = threadIdx.x;
    int lane = tid & 31, wrp = tid >> 5;

    size_t base = ((size_t)(w * NHEAD + h)) * NTOK * HDIM;
    for (int f = tid; f < 392; f += 256) {
        ((float4*)qs)[f] = ((const float4*)(g_q + base))[f];
        ((float4*)vs)[f] = ((const float4*)(g_v + base))[f];
        float4 kv = ((const float4*)(g_k + base))[f];
        int m = f >> 3, d = (f & 7) << 2;
        ksT[(d + 0) * 57 + m] = kv.x;
        ksT[(d + 1) * 57 + m] = kv.y;
        ksT[(d + 2) * 57 + m] = kv.z;
        ksT[(d + 3) * 57 + m] = kv.w;
    }
    __syncthreads();

    int wi = w & 63;
    const float* bia = g_bias6 + h * (NTOK * NTOK);
    const float* msk = mask + (size_t)wi * (NTOK * NTOK);

    bool v1 = (lane + 32) < NTOK;   // 17 valid lanes in second chunk

    for (int row = wrp; row < NTOK; row += 8) {
        float x0 = 0.f, x1 = 0.f;
        const float* qp = qs + row * HDIM;
#pragma unroll
        for (int d = 0; d < HDIM; d++) {
            float qv = qp[d];
            x0 = fmaf(qv, ksT[d * 57 + lane], x0);
            x1 = fmaf(qv, ksT[d * 57 + lane + 32], x1);
        }
        int e0 = row * NTOK + lane;
        x0 += bia[e0] + msk[e0];
        if (v1) x1 += bia[e0 + 32] + msk[e0 + 32];
        else    x1 = -1e30f;

        float mx = fmaxf(x0, x1);
#pragma unroll
        for (int off = 16; off; off >>= 1)
            mx = fmaxf(mx, __shfl_xor_sync(0xFFFFFFFFu, mx, off));
        float ex0 = __expf(x0 - mx);
        float ex1 = v1 ? __expf(x1 - mx) : 0.f;
        float sum = ex0 + ex1;
#pragma unroll
        for (int off = 16; off; off >>= 1)
            sum += __shfl_xor_sync(0xFFFFFFFFu, sum, off);
        float inv = 1.f / sum;
        ps[e0] = ex0 * inv;
        if (v1) ps[e0 + 32] = ex1 * inv;
    }
    __syncthreads();

    // ctx = probs @ v  (lane = d: conflict-free, pr[m] broadcast)
    float* op = g_ctx + (size_t)w * NTOK * CCH + h * HDIM;
    for (int e = tid; e < NTOK * HDIM; e += 256) {
        int n = e >> 5, d = e & 31;
        float s = 0.f;
        const float* pr = ps + n * NTOK;
#pragma unroll
        for (int m = 0; m < NTOK; m++) s = fmaf(pr[m], vs[m * HDIM + d], s);
        op[n * CCH + d] = s;
    }
}

// ---------------- launch ----------------
extern "C" void kernel_launch(void* const* d_in, const int* in_sizes, int n_in,
                              void* d_out, int out_size)
{
    const float* inputs = (const float*)d_in[0];
    const float* amask  = (const float*)d_in[1];
    const float* n1g    = (const float*)d_in[2];
    const float* n1b    = (const float*)d_in[3];
    const float* qkvw   = (const float*)d_in[4];
    const float* qkvb   = (const float*)d_in[5];
    const float* rpt    = (const float*)d_in[6];
    const int*   rpi    = (const int*)d_in[7];
    const float* pw     = (const float*)d_in[8];
    const float* pb     = (const float*)d_in[9];
    const float* lw     = (const float*)d_in[10];
    const float* lb     = (const float*)d_in[11];
    float* out = (float*)d_out;

    bias_kernel<<<(NHEAD * NTOK * NTOK + 255) / 256, 256>>>(rpt, rpi);
    ln_kernel<<<TOK / 8, 256>>>(inputs, n1g, n1b);
    gemm_kernel<0><<<dim3(TOK / 128, 9), 256>>>(qkvw, qkvb, nullptr, nullptr);
    attn_kernel<<<dim3(BWIN, NHEAD), 256>>>(amask);
    gemm_kernel<1><<<dim3(TOK / 128, 3), 256>>>(pw, pb, nullptr, nullptr);
    gemm_kernel<2><<<dim3(TOK / 128, 3), 256>>>(lw, lb, inputs, out);
}

// round 4
// speedup vs baseline: 6.3100x; 1.2750x over previous
#include <cuda_runtime.h>
#include <math.h>

// Problem constants
#define B_IMG   32
#define HW      56
#define CCH     192
#define NHEAD   6
#define HDIM    32
#define NTOK    49
#define NWIN    64
#define BWIN    2048
#define TOK     100352
#define SHIFT_  3
#define QSCALE  0.17677669529663687f

// ---------------- scratch ----------------
__device__ float g_xw [ (size_t)TOK * CCH ];
__device__ float g_q  [ (size_t)BWIN * NHEAD * NTOK * HDIM ];
__device__ float g_k  [ (size_t)BWIN * NHEAD * NTOK * HDIM ];
__device__ float g_v  [ (size_t)BWIN * NHEAD * NTOK * HDIM ];
__device__ float g_ctx[ (size_t)TOK * CCH ];
__device__ float g_y  [ (size_t)TOK * CCH ];
__device__ float g_bias6[ NHEAD * NTOK * NTOK ];

// ---------------- K0: rel-pos bias gather ----------------
__global__ void bias_kernel(const float* __restrict__ table, const int* __restrict__ idx)
{
    int i = blockIdx.x * blockDim.x + threadIdx.x;
    if (i < NHEAD * NTOK * NTOK) {
        int h = i / (NTOK * NTOK);
        int e = i % (NTOK * NTOK);
        g_bias6[i] = table[idx[e] * NHEAD + h];
    }
}

// ---------------- K1: LN + shift + window partition ----------------
__global__ void __launch_bounds__(256) ln_kernel(const float* __restrict__ x,
                                                 const float* __restrict__ g,
                                                 const float* __restrict__ b)
{
    int wid  = (blockIdx.x * blockDim.x + threadIdx.x) >> 5;
    int lane = threadIdx.x & 31;
    if (wid >= TOK) return;

    int w  = wid / NTOK, n = wid % NTOK;
    int bb = w >> 6, wi = w & 63;
    int wh = wi >> 3, ww = wi & 7;
    int ii = n / 7,  jj = n % 7;
    int hh = (wh * 7 + ii + SHIFT_) % HW;
    int w2 = (ww * 7 + jj + SHIFT_) % HW;
    const float* src = x + ((size_t)bb * (HW * HW) + hh * HW + w2) * CCH;

    float vals[6];
    float s = 0.f, s2 = 0.f;
#pragma unroll
    for (int u = 0; u < 6; u++) {
        float v = src[lane + u * 32];
        vals[u] = v; s += v; s2 += v * v;
    }
#pragma unroll
    for (int off = 16; off; off >>= 1) {
        s  += __shfl_xor_sync(0xFFFFFFFFu, s,  off);
        s2 += __shfl_xor_sync(0xFFFFFFFFu, s2, off);
    }
    float mu  = s * (1.f / CCH);
    float var = s2 * (1.f / CCH) - mu * mu;
    float inv = rsqrtf(var + 1e-5f);

    float* dst = g_xw + (size_t)wid * CCH;
#pragma unroll
    for (int u = 0; u < 6; u++) {
        int c = lane + u * 32;
        dst[c] = (vals[u] - mu) * inv * g[c] + b[c];
    }
}

// ---------------- tf32 helpers ----------------
__device__ __forceinline__ float to_tf32(float x) {
    unsigned u;
    asm("cvt.rna.tf32.f32 %0, %1;" : "=r"(u) : "f"(x));
    return __uint_as_float(u);
}
__device__ __forceinline__ unsigned tf32u(float x) {
    unsigned u;
    asm("cvt.rna.tf32.f32 %0, %1;" : "=r"(u) : "f"(x));
    return u;
}

__device__ __forceinline__ void mma_tf32(float* d, const unsigned* a, const unsigned* b) {
    asm volatile(
        "mma.sync.aligned.m16n8k8.row.col.f32.tf32.tf32.f32 "
        "{%0,%1,%2,%3}, {%4,%5,%6,%7}, {%8,%9}, {%0,%1,%2,%3};\n"
        : "+f"(d[0]), "+f"(d[1]), "+f"(d[2]), "+f"(d[3])
        : "r"(a[0]), "r"(a[1]), "r"(a[2]), "r"(a[3]), "r"(b[0]), "r"(b[1]));
}

// ---------------- tf32 MMA GEMM: out = A[M,192] @ W[N,192]^T + epilogue -----
template<int EPI>
__global__ void __launch_bounds__(256) gemm_kernel(const float* __restrict__ W,
                                                   const float* __restrict__ bias,
                                                   const float* __restrict__ resid,
                                                   float* __restrict__ out)
{
    const float* A = (EPI == 0) ? g_xw : (EPI == 1 ? g_ctx : g_y);

    __shared__ __align__(16) float As[128 * 36];
    __shared__ __align__(16) float Bs[64 * 36];

    int tid  = threadIdx.x;
    int lane = tid & 31, wid = tid >> 5;
    int wm = wid >> 1, wn = wid & 1;
    int gid = lane >> 2, qid = lane & 3;
    int row0 = blockIdx.x * 128;
    int col0 = blockIdx.y * 64;

    float acc[2][4][4];
#pragma unroll
    for (int i = 0; i < 2; i++)
#pragma unroll
        for (int j = 0; j < 4; j++)
#pragma unroll
            for (int r = 0; r < 4; r++) acc[i][j][r] = 0.f;

    for (int k0 = 0; k0 < CCH; k0 += 32) {
#pragma unroll
        for (int i = 0; i < 4; i++) {
            int f = tid + i * 256;
            int r = f >> 3, kk = (f & 7) << 2;
            float4 v = *(const float4*)(A + (size_t)(row0 + r) * CCH + k0 + kk);
            float4 c = make_float4(to_tf32(v.x), to_tf32(v.y), to_tf32(v.z), to_tf32(v.w));
            *(float4*)&As[r * 36 + kk] = c;
        }
#pragma unroll
        for (int i = 0; i < 2; i++) {
            int f = tid + i * 256;
            int r = f >> 3, kk = (f & 7) << 2;
            float4 v = *(const float4*)(W + (size_t)(col0 + r) * CCH + k0 + kk);
            float4 c = make_float4(to_tf32(v.x), to_tf32(v.y), to_tf32(v.z), to_tf32(v.w));
            *(float4*)&Bs[r * 36 + kk] = c;
        }
        __syncthreads();

#pragma unroll
        for (int ks = 0; ks < 32; ks += 8) {
            unsigned af[2][4], bf[4][2];
#pragma unroll
            for (int mi = 0; mi < 2; mi++) {
                int r = wm * 32 + mi * 16 + gid;
                af[mi][0] = __float_as_uint(As[r * 36 + ks + qid]);
                af[mi][1] = __float_as_uint(As[(r + 8) * 36 + ks + qid]);
                af[mi][2] = __float_as_uint(As[r * 36 + ks + qid + 4]);
                af[mi][3] = __float_as_uint(As[(r + 8) * 36 + ks + qid + 4]);
            }
#pragma unroll
            for (int ni = 0; ni < 4; ni++) {
                int n = wn * 32 + ni * 8 + gid;
                bf[ni][0] = __float_as_uint(Bs[n * 36 + ks + qid]);
                bf[ni][1] = __float_as_uint(Bs[n * 36 + ks + qid + 4]);
            }
#pragma unroll
            for (int mi = 0; mi < 2; mi++)
#pragma unroll
                for (int ni = 0; ni < 4; ni++)
                    mma_tf32(acc[mi][ni], af[mi], bf[ni]);
        }
        __syncthreads();
    }

#pragma unroll
    for (int mi = 0; mi < 2; mi++) {
#pragma unroll
        for (int reg = 0; reg < 4; reg++) {
            int r = row0 + wm * 32 + mi * 16 + gid + ((reg >= 2) ? 8 : 0);
            int w = r / NTOK, n = r % NTOK;
            if (EPI == 0) {
#pragma unroll
                for (int ni = 0; ni < 4; ni++) {
                    int o = col0 + wn * 32 + ni * 8 + qid * 2 + (reg & 1);
                    float val = acc[mi][ni][reg] + bias[o];
                    int m = o / CCH, rem = o % CCH;
                    int h = rem >> 5, d = rem & 31;
                    size_t idx = (((size_t)(w * NHEAD + h)) * NTOK + n) * HDIM + d;
                    if (m == 0)      g_q[idx] = val * QSCALE;
                    else if (m == 1) g_k[idx] = val;
                    else             g_v[idx] = val;
                }
            } else if (EPI == 1) {
                int bb = w >> 6, wi = w & 63;
                int wh = wi >> 3, ww = wi & 7;
                int ii = n / 7, jj = n % 7;
                int hh = (wh * 7 + ii + SHIFT_) % HW;
                int w2 = (ww * 7 + jj + SHIFT_) % HW;
                float* dst = g_y + ((size_t)bb * (HW * HW) + hh * HW + w2) * CCH;
#pragma unroll
                for (int ni = 0; ni < 4; ni++) {
                    int c = col0 + wn * 32 + ni * 8 + qid * 2 + (reg & 1);
                    dst[c] = acc[mi][ni][reg] + bias[c];
                }
            } else {
                const float* rs = resid + (size_t)r * CCH;
                float* dp = out + (size_t)r * CCH;
#pragma unroll
                for (int ni = 0; ni < 4; ni++) {
                    int c = col0 + wn * 32 + ni * 8 + qid * 2 + (reg & 1);
                    float v = acc[mi][ni][reg] + bias[c];
                    float ge = 0.5f * v * (1.f + erff(v * 0.70710678118654752f));
                    dp[c] = rs[c] + ge;
                }
            }
        }
    }
}

// ---------------- K3: windowed attention via warp MMA -----------------------
// 128 threads, warp w owns query rows [16w, 16w+16). M padded to 64,
// N (keys) padded to 56; padded score cols masked to -1e9 via bm table.
__global__ void __launch_bounds__(128) attn_kernel(const float* __restrict__ mask)
{
    __shared__ __align__(16) float qs[64 * 36];
    __shared__ __align__(16) float ks[56 * 36];
    __shared__ __align__(16) float vs[56 * 40];
    __shared__ __align__(8)  float bm[64 * 60];

    int w = blockIdx.x, h = blockIdx.y;
    int tid = threadIdx.x;
    int lane = tid & 31, wrp = tid >> 5;
    int gid = lane >> 2, qid = lane & 3;

    size_t base = ((size_t)(w * NHEAD + h)) * NTOK * HDIM;
    const float4* q4 = (const float4*)(g_q + base);
    const float4* k4 = (const float4*)(g_k + base);
    const float4* v4 = (const float4*)(g_v + base);
    for (int f = tid; f < 392; f += 128) {
        int r = f >> 3, c = (f & 7) << 2;
        *(float4*)&qs[r * 36 + c] = q4[f];
        *(float4*)&ks[r * 36 + c] = k4[f];
        *(float4*)&vs[r * 40 + c] = v4[f];
    }
    // zero K,V pad rows 49..55 (avoid NaN garbage entering masked scores)
    for (int f = tid; f < 7 * 36; f += 128) ks[(49 + f / 36) * 36 + (f % 36)] = 0.f;
    for (int f = tid; f < 7 * 40; f += 128) vs[(49 + f / 40) * 40 + (f % 40)] = 0.f;
    // combined bias+mask table, padded region = -1e9
    {
        const float* bia = g_bias6 + h * (NTOK * NTOK);
        const float* msk = mask + (size_t)(w & 63) * (NTOK * NTOK);
        for (int f = tid; f < 64 * 56; f += 128) {
            int r = f / 56, c = f % 56;
            float v = (r < NTOK && c < NTOK) ? (bia[r * NTOK + c] + msk[r * NTOK + c]) : -1e9f;
            bm[r * 60 + c] = v;
        }
    }
    __syncthreads();

    int m0 = wrp * 16;

    // ---- S = Q K^T ----
    float sacc[7][4];
#pragma unroll
    for (int nt = 0; nt < 7; nt++)
#pragma unroll
        for (int r = 0; r < 4; r++) sacc[nt][r] = 0.f;

#pragma unroll
    for (int kt = 0; kt < 4; kt++) {
        int k0 = kt * 8;
        unsigned a[4];
        a[0] = tf32u(qs[(m0 + gid) * 36 + k0 + qid]);
        a[1] = tf32u(qs[(m0 + gid + 8) * 36 + k0 + qid]);
        a[2] = tf32u(qs[(m0 + gid) * 36 + k0 + qid + 4]);
        a[3] = tf32u(qs[(m0 + gid + 8) * 36 + k0 + qid + 4]);
#pragma unroll
        for (int nt = 0; nt < 7; nt++) {
            unsigned b[2];
            b[0] = tf32u(ks[(nt * 8 + gid) * 36 + k0 + qid]);
            b[1] = tf32u(ks[(nt * 8 + gid) * 36 + k0 + qid + 4]);
            mma_tf32(sacc[nt], a, b);
        }
    }

    // ---- + bias + mask ----
#pragma unroll
    for (int nt = 0; nt < 7; nt++) {
        float2 t0 = *(const float2*)&bm[(m0 + gid) * 60 + nt * 8 + 2 * qid];
        float2 t1 = *(const float2*)&bm[(m0 + gid + 8) * 60 + nt * 8 + 2 * qid];
        sacc[nt][0] += t0.x; sacc[nt][1] += t0.y;
        sacc[nt][2] += t1.x; sacc[nt][3] += t1.y;
    }

    // ---- softmax in registers (row r0 = regs 0,1; row r1 = regs 2,3) ----
    float mx0 = -1e30f, mx1 = -1e30f;
#pragma unroll
    for (int nt = 0; nt < 7; nt++) {
        mx0 = fmaxf(mx0, fmaxf(sacc[nt][0], sacc[nt][1]));
        mx1 = fmaxf(mx1, fmaxf(sacc[nt][2], sacc[nt][3]));
    }
    mx0 = fmaxf(mx0, __shfl_xor_sync(0xFFFFFFFFu, mx0, 1));
    mx0 = fmaxf(mx0, __shfl_xor_sync(0xFFFFFFFFu, mx0, 2));
    mx1 = fmaxf(mx1, __shfl_xor_sync(0xFFFFFFFFu, mx1, 1));
    mx1 = fmaxf(mx1, __shfl_xor_sync(0xFFFFFFFFu, mx1, 2));

    float sum0 = 0.f, sum1 = 0.f;
#pragma unroll
    for (int nt = 0; nt < 7; nt++) {
        sacc[nt][0] = __expf(sacc[nt][0] - mx0);
        sacc[nt][1] = __expf(sacc[nt][1] - mx0);
        sacc[nt][2] = __expf(sacc[nt][2] - mx1);
        sacc[nt][3] = __expf(sacc[nt][3] - mx1);
        sum0 += sacc[nt][0] + sacc[nt][1];
        sum1 += sacc[nt][2] + sacc[nt][3];
    }
    sum0 += __shfl_xor_sync(0xFFFFFFFFu, sum0, 1);
    sum0 += __shfl_xor_sync(0xFFFFFFFFu, sum0, 2);
    sum1 += __shfl_xor_sync(0xFFFFFFFFu, sum1, 1);
    sum1 += __shfl_xor_sync(0xFFFFFFFFu, sum1, 2);
    float inv0 = 1.f / sum0, inv1 = 1.f / sum1;
#pragma unroll
    for (int nt = 0; nt < 7; nt++) {
        sacc[nt][0] *= inv0; sacc[nt][1] *= inv0;
        sacc[nt][2] *= inv1; sacc[nt][3] *= inv1;
    }

    // ---- O = P V : re-fragment P via shuffles (no smem round-trip) ----
    float o[4][4];
#pragma unroll
    for (int nt = 0; nt < 4; nt++)
#pragma unroll
        for (int r = 0; r < 4; r++) o[nt][r] = 0.f;

    int src0 = (lane & ~3) | (qid >> 1);
    int src1 = src0 + 2;
    bool odd = (qid & 1);

#pragma unroll
    for (int kt = 0; kt < 7; kt++) {
        float p00 = __shfl_sync(0xFFFFFFFFu, sacc[kt][0], src0);
        float p01 = __shfl_sync(0xFFFFFFFFu, sacc[kt][1], src0);
        float p10 = __shfl_sync(0xFFFFFFFFu, sacc[kt][0], src1);
        float p11 = __shfl_sync(0xFFFFFFFFu, sacc[kt][1], src1);
        float p20 = __shfl_sync(0xFFFFFFFFu, sacc[kt][2], src0);
        float p21 = __shfl_sync(0xFFFFFFFFu, sacc[kt][3], src0);
        float p30 = __shfl_sync(0xFFFFFFFFu, sacc[kt][2], src1);
        float p31 = __shfl_sync(0xFFFFFFFFu, sacc[kt][3], src1);
        unsigned a[4];
        a[0] = tf32u(odd ? p01 : p00);
        a[1] = tf32u(odd ? p21 : p20);
        a[2] = tf32u(odd ? p11 : p10);
        a[3] = tf32u(odd ? p31 : p30);
#pragma unroll
        for (int nt = 0; nt < 4; nt++) {
            unsigned b[2];
            b[0] = tf32u(vs[(kt * 8 + qid) * 40 + nt * 8 + gid]);
            b[1] = tf32u(vs[(kt * 8 + qid + 4) * 40 + nt * 8 + gid]);
            mma_tf32(o[nt], a, b);
        }
    }

    // ---- write ctx ----
    int r0 = m0 + gid, r1 = r0 + 8;
    float* op = g_ctx + ((size_t)w * NTOK) * CCH + h * HDIM;
#pragma unroll
    for (int nt = 0; nt < 4; nt++) {
        int d = nt * 8 + 2 * qid;
        if (r0 < NTOK) { float2 t = make_float2(o[nt][0], o[nt][1]); *(float2*)&op[r0 * CCH + d] = t; }
        if (r1 < NTOK) { float2 t = make_float2(o[nt][2], o[nt][3]); *(float2*)&op[r1 * CCH + d] = t; }
    }
}

// ---------------- launch ----------------
extern "C" void kernel_launch(void* const* d_in, const int* in_sizes, int n_in,
                              void* d_out, int out_size)
{
    const float* inputs = (const float*)d_in[0];
    const float* amask  = (const float*)d_in[1];
    const float* n1g    = (const float*)d_in[2];
    const float* n1b    = (const float*)d_in[3];
    const float* qkvw   = (const float*)d_in[4];
    const float* qkvb   = (const float*)d_in[5];
    const float* rpt    = (const float*)d_in[6];
    const int*   rpi    = (const int*)d_in[7];
    const float* pw     = (const float*)d_in[8];
    const float* pb     = (const float*)d_in[9];
    const float* lw     = (const float*)d_in[10];
    const float* lb     = (const float*)d_in[11];
    float* out = (float*)d_out;

    bias_kernel<<<(NHEAD * NTOK * NTOK + 255) / 256, 256>>>(rpt, rpi);
    ln_kernel<<<TOK / 8, 256>>>(inputs, n1g, n1b);
    gemm_kernel<0><<<dim3(TOK / 128, 9), 256>>>(qkvw, qkvb, nullptr, nullptr);
    attn_kernel<<<dim3(BWIN, NHEAD), 128>>>(amask);
    gemm_kernel<1><<<dim3(TOK / 128, 3), 256>>>(pw, pb, nullptr, nullptr);
    gemm_kernel<2><<<dim3(TOK / 128, 3), 256>>>(lw, lb, inputs, out);
}

// round 5
// speedup vs baseline: 6.6594x; 1.0554x over previous
#include <cuda_runtime.h>
#include <math.h>

// Problem constants
#define B_IMG   32
#define HW      56
#define CCH     192
#define NHEAD   6
#define HDIM    32
#define NTOK    49
#define NWIN    64
#define BWIN    2048
#define TOK     100352
#define SHIFT_  3
#define QSCALE  0.17677669529663687f

// ---------------- scratch ----------------
__device__ float g_xw [ (size_t)TOK * CCH ];
__device__ float g_q  [ (size_t)BWIN * NHEAD * NTOK * HDIM ];
__device__ float g_k  [ (size_t)BWIN * NHEAD * NTOK * HDIM ];
__device__ float g_v  [ (size_t)BWIN * NHEAD * NTOK * HDIM ];
__device__ float g_ctx[ (size_t)TOK * CCH ];
__device__ float g_y  [ (size_t)TOK * CCH ];
__device__ float g_bias6[ NHEAD * NTOK * NTOK ];

// ---------------- K0: rel-pos bias gather ----------------
__global__ void bias_kernel(const float* __restrict__ table, const int* __restrict__ idx)
{
    int i = blockIdx.x * blockDim.x + threadIdx.x;
    if (i < NHEAD * NTOK * NTOK) {
        int h = i / (NTOK * NTOK);
        int e = i % (NTOK * NTOK);
        g_bias6[i] = table[idx[e] * NHEAD + h];
    }
}

// ---------------- K1: LN + shift + window partition ----------------
__global__ void __launch_bounds__(256) ln_kernel(const float* __restrict__ x,
                                                 const float* __restrict__ g,
                                                 const float* __restrict__ b)
{
    int wid  = (blockIdx.x * blockDim.x + threadIdx.x) >> 5;
    int lane = threadIdx.x & 31;
    if (wid >= TOK) return;

    int w  = wid / NTOK, n = wid % NTOK;
    int bb = w >> 6, wi = w & 63;
    int wh = wi >> 3, ww = wi & 7;
    int ii = n / 7,  jj = n % 7;
    int hh = (wh * 7 + ii + SHIFT_) % HW;
    int w2 = (ww * 7 + jj + SHIFT_) % HW;
    const float* src = x + ((size_t)bb * (HW * HW) + hh * HW + w2) * CCH;

    float vals[6];
    float s = 0.f, s2 = 0.f;
#pragma unroll
    for (int u = 0; u < 6; u++) {
        float v = src[lane + u * 32];
        vals[u] = v; s += v; s2 += v * v;
    }
#pragma unroll
    for (int off = 16; off; off >>= 1) {
        s  += __shfl_xor_sync(0xFFFFFFFFu, s,  off);
        s2 += __shfl_xor_sync(0xFFFFFFFFu, s2, off);
    }
    float mu  = s * (1.f / CCH);
    float var = s2 * (1.f / CCH) - mu * mu;
    float inv = rsqrtf(var + 1e-5f);

    float* dst = g_xw + (size_t)wid * CCH;
#pragma unroll
    for (int u = 0; u < 6; u++) {
        int c = lane + u * 32;
        dst[c] = (vals[u] - mu) * inv * g[c] + b[c];
    }
}

// ---------------- tf32 helpers ----------------
__device__ __forceinline__ float to_tf32(float x) {
    unsigned u;
    asm("cvt.rna.tf32.f32 %0, %1;" : "=r"(u) : "f"(x));
    return __uint_as_float(u);
}
__device__ __forceinline__ unsigned tf32u(float x) {
    unsigned u;
    asm("cvt.rna.tf32.f32 %0, %1;" : "=r"(u) : "f"(x));
    return u;
}

__device__ __forceinline__ void mma_tf32(float* d, const unsigned* a, const unsigned* b) {
    asm volatile(
        "mma.sync.aligned.m16n8k8.row.col.f32.tf32.tf32.f32 "
        "{%0,%1,%2,%3}, {%4,%5,%6,%7}, {%8,%9}, {%0,%1,%2,%3};\n"
        : "+f"(d[0]), "+f"(d[1]), "+f"(d[2]), "+f"(d[3])
        : "r"(a[0]), "r"(a[1]), "r"(a[2]), "r"(a[3]), "r"(b[0]), "r"(b[1]));
}

// Fragment-swizzled smem layouts:
//  A/Q ("row" operand, 16-row groups): blk=(mgrp*NKG+kgrp), stride 132
//    idx = blk*132 + (r&7)*16 + ((r>>3)&1) + (((k>>2)&1)<<1) + (k&3)*4
//    -> per-thread fragment = one LDS.128 at blk*132 + lane*4
//  B/K/V ("col" operand, 8-row groups): blk=(ngrp*NKG+kgrp), stride 68
//    idx = blk*68 + ((n&7)*4 + (k&3))*2 + ((k>>2)&1)
//    -> per-thread fragment = one LDS.64 at blk*68 + lane*2

// ---------------- tf32 MMA GEMM: out = A[M,192] @ W[N,192]^T + epilogue -----
// grid (cols, rows) so CTAs sharing an A-tile are adjacent (L2 reuse).
template<int EPI>
__global__ void __launch_bounds__(256) gemm_kernel(const float* __restrict__ W,
                                                   const float* __restrict__ bias,
                                                   const float* __restrict__ resid,
                                                   float* __restrict__ out)
{
    const float* A = (EPI == 0) ? g_xw : (EPI == 1 ? g_ctx : g_y);

    __shared__ __align__(16) float As[32 * 132];   // 8 mgrp x 4 kgrp
    __shared__ __align__(16) float Bs[32 * 68];    // 8 ngrp x 4 kgrp

    int tid  = threadIdx.x;
    int lane = tid & 31, wid = tid >> 5;
    int wm = wid >> 1, wn = wid & 1;
    int gid = lane >> 2, qid = lane & 3;
    int row0 = blockIdx.y * 128;
    int col0 = blockIdx.x * 64;

    float acc[2][4][4];
#pragma unroll
    for (int i = 0; i < 2; i++)
#pragma unroll
        for (int j = 0; j < 4; j++)
#pragma unroll
            for (int r = 0; r < 4; r++) acc[i][j][r] = 0.f;

    float4 a_ld[4], b_ld[2];
#pragma unroll
    for (int i = 0; i < 4; i++) {
        int f = tid + i * 256;
        a_ld[i] = *(const float4*)(A + (size_t)(row0 + (f >> 3)) * CCH + ((f & 7) << 2));
    }
#pragma unroll
    for (int i = 0; i < 2; i++) {
        int f = tid + i * 256;
        b_ld[i] = *(const float4*)(W + (size_t)(col0 + (f >> 3)) * CCH + ((f & 7) << 2));
    }

    for (int k0 = 0; k0 < CCH; k0 += 32) {
        // store staged regs (tf32-converted, fragment-swizzled)
#pragma unroll
        for (int i = 0; i < 4; i++) {
            int f = tid + i * 256;
            int r = f >> 3, kk = (f & 7) << 2;
            int off = ((r >> 4) * 4 + (kk >> 3)) * 132 + (r & 7) * 16
                    + ((r >> 3) & 1) + (((kk >> 2) & 1) << 1);
            As[off +  0] = to_tf32(a_ld[i].x);
            As[off +  4] = to_tf32(a_ld[i].y);
            As[off +  8] = to_tf32(a_ld[i].z);
            As[off + 12] = to_tf32(a_ld[i].w);
        }
#pragma unroll
        for (int i = 0; i < 2; i++) {
            int f = tid + i * 256;
            int r = f >> 3, kk = (f & 7) << 2;
            int off = ((r >> 3) * 4 + (kk >> 3)) * 68 + (r & 7) * 8 + ((kk >> 2) & 1);
            Bs[off + 0] = to_tf32(b_ld[i].x);
            Bs[off + 2] = to_tf32(b_ld[i].y);
            Bs[off + 4] = to_tf32(b_ld[i].z);
            Bs[off + 6] = to_tf32(b_ld[i].w);
        }
        __syncthreads();

        // prefetch next tile into regs
        if (k0 + 32 < CCH) {
#pragma unroll
            for (int i = 0; i < 4; i++) {
                int f = tid + i * 256;
                a_ld[i] = *(const float4*)(A + (size_t)(row0 + (f >> 3)) * CCH + k0 + 32 + ((f & 7) << 2));
            }
#pragma unroll
            for (int i = 0; i < 2; i++) {
                int f = tid + i * 256;
                b_ld[i] = *(const float4*)(W + (size_t)(col0 + (f >> 3)) * CCH + k0 + 32 + ((f & 7) << 2));
            }
        }

#pragma unroll
        for (int ks8 = 0; ks8 < 4; ks8++) {
            float4 af0 = *(const float4*)&As[((wm * 2 + 0) * 4 + ks8) * 132 + lane * 4];
            float4 af1 = *(const float4*)&As[((wm * 2 + 1) * 4 + ks8) * 132 + lane * 4];
            float2 bf[4];
#pragma unroll
            for (int ni = 0; ni < 4; ni++)
                bf[ni] = *(const float2*)&Bs[((wn * 4 + ni) * 4 + ks8) * 68 + lane * 2];
#pragma unroll
            for (int ni = 0; ni < 4; ni++) {
                mma_tf32(acc[0][ni], (const unsigned*)&af0, (const unsigned*)&bf[ni]);
                mma_tf32(acc[1][ni], (const unsigned*)&af1, (const unsigned*)&bf[ni]);
            }
        }
        __syncthreads();
    }

#pragma unroll
    for (int mi = 0; mi < 2; mi++) {
#pragma unroll
        for (int reg = 0; reg < 4; reg++) {
            int r = row0 + wm * 32 + mi * 16 + gid + ((reg >= 2) ? 8 : 0);
            int w = r / NTOK, n = r % NTOK;
            if (EPI == 0) {
#pragma unroll
                for (int ni = 0; ni < 4; ni++) {
                    int o = col0 + wn * 32 + ni * 8 + qid * 2 + (reg & 1);
                    float val = acc[mi][ni][reg] + bias[o];
                    int m = o / CCH, rem = o % CCH;
                    int h = rem >> 5, d = rem & 31;
                    size_t idx = (((size_t)(w * NHEAD + h)) * NTOK + n) * HDIM + d;
                    if (m == 0)      g_q[idx] = val * QSCALE;
                    else if (m == 1) g_k[idx] = val;
                    else             g_v[idx] = val;
                }
            } else if (EPI == 1) {
                int bb = w >> 6, wi = w & 63;
                int wh = wi >> 3, ww = wi & 7;
                int ii = n / 7, jj = n % 7;
                int hh = (wh * 7 + ii + SHIFT_) % HW;
                int w2 = (ww * 7 + jj + SHIFT_) % HW;
                float* dst = g_y + ((size_t)bb * (HW * HW) + hh * HW + w2) * CCH;
#pragma unroll
                for (int ni = 0; ni < 4; ni++) {
                    int c = col0 + wn * 32 + ni * 8 + qid * 2 + (reg & 1);
                    dst[c] = acc[mi][ni][reg] + bias[c];
                }
            } else {
                const float* rs = resid + (size_t)r * CCH;
                float* dp = out + (size_t)r * CCH;
#pragma unroll
                for (int ni = 0; ni < 4; ni++) {
                    int c = col0 + wn * 32 + ni * 8 + qid * 2 + (reg & 1);
                    float v = acc[mi][ni][reg] + bias[c];
                    float ge = 0.5f * v * (1.f + erff(v * 0.70710678118654752f));
                    dp[c] = rs[c] + ge;
                }
            }
        }
    }
}

// ---------------- K3: windowed attention via warp MMA (swizzled, tf32-pre) --
__global__ void __launch_bounds__(128) attn_kernel(const float* __restrict__ mask)
{
    __shared__ __align__(16) float qs[16 * 132];   // 4 mgrp x 4 kgrp
    __shared__ __align__(16) float ks[28 * 68];    // 7 ngrp x 4 kgrp
    __shared__ __align__(16) float vs[28 * 68];    // 7 kgrp x 4 ngrp
    __shared__ __align__(8)  float bm[64 * 60];

    int w = blockIdx.x, h = blockIdx.y;
    int tid = threadIdx.x;
    int lane = tid & 31, wrp = tid >> 5;
    int gid = lane >> 2, qid = lane & 3;

    // zero pad blocks (Q rows 49-63 live in blocks 12-15; K/V rows 48-55 in 24-27,
    // row 48 data is rewritten after the barrier)
    for (int f = tid; f < 4 * 132; f += 128) qs[12 * 132 + f] = 0.f;
    for (int f = tid; f < 4 * 68; f += 128) { ks[24 * 68 + f] = 0.f; vs[24 * 68 + f] = 0.f; }
    __syncthreads();

    size_t base = ((size_t)(w * NHEAD + h)) * NTOK * HDIM;
    const float4* q4 = (const float4*)(g_q + base);
    const float4* k4 = (const float4*)(g_k + base);
    const float4* v4 = (const float4*)(g_v + base);
    for (int f = tid; f < 392; f += 128) {
        int r = f >> 3, c = (f & 7) << 2;
        float4 qv = q4[f], kv = k4[f], vv = v4[f];
        int qo = ((r >> 4) * 4 + (c >> 3)) * 132 + (r & 7) * 16
               + ((r >> 3) & 1) + (((c >> 2) & 1) << 1);
        qs[qo + 0] = to_tf32(qv.x); qs[qo + 4] = to_tf32(qv.y);
        qs[qo + 8] = to_tf32(qv.z); qs[qo + 12] = to_tf32(qv.w);
        int ko = ((r >> 3) * 4 + (c >> 3)) * 68 + (r & 7) * 8 + ((c >> 2) & 1);
        ks[ko + 0] = to_tf32(kv.x); ks[ko + 2] = to_tf32(kv.y);
        ks[ko + 4] = to_tf32(kv.z); ks[ko + 6] = to_tf32(kv.w);
        // V: rows are K-dim, cols are N-dim
        int vo = ((r >> 3) * 4 + (c >> 3)) * 68 + (c & 7) * 8 + (r & 3) * 2 + ((r >> 2) & 1);
        vs[vo + 0] = to_tf32(vv.x); vs[vo + 8] = to_tf32(vv.y);
        vs[vo + 16] = to_tf32(vv.z); vs[vo + 24] = to_tf32(vv.w);
    }
    {
        const float* bia = g_bias6 + h * (NTOK * NTOK);
        const float* msk = mask + (size_t)(w & 63) * (NTOK * NTOK);
        for (int f = tid; f < 64 * 56; f += 128) {
            int r = f / 56, c = f % 56;
            float v = (r < NTOK && c < NTOK) ? (bia[r * NTOK + c] + msk[r * NTOK + c]) : -1e9f;
            bm[r * 60 + c] = v;
        }
    }
    __syncthreads();

    int m0 = wrp * 16;

    // ---- S = Q K^T ----
    float sacc[7][4];
#pragma unroll
    for (int nt = 0; nt < 7; nt++)
#pragma unroll
        for (int r = 0; r < 4; r++) sacc[nt][r] = 0.f;

#pragma unroll
    for (int kt = 0; kt < 4; kt++) {
        float4 av = *(const float4*)&qs[(wrp * 4 + kt) * 132 + lane * 4];
#pragma unroll
        for (int nt = 0; nt < 7; nt++) {
            float2 bv = *(const float2*)&ks[(nt * 4 + kt) * 68 + lane * 2];
            mma_tf32(sacc[nt], (const unsigned*)&av, (const unsigned*)&bv);
        }
    }

    // ---- + bias + mask ----
#pragma unroll
    for (int nt = 0; nt < 7; nt++) {
        float2 t0 = *(const float2*)&bm[(m0 + gid) * 60 + nt * 8 + 2 * qid];
        float2 t1 = *(const float2*)&bm[(m0 + gid + 8) * 60 + nt * 8 + 2 * qid];
        sacc[nt][0] += t0.x; sacc[nt][1] += t0.y;
        sacc[nt][2] += t1.x; sacc[nt][3] += t1.y;
    }

    // ---- softmax in registers ----
    float mx0 = -1e30f, mx1 = -1e30f;
#pragma unroll
    for (int nt = 0; nt < 7; nt++) {
        mx0 = fmaxf(mx0, fmaxf(sacc[nt][0], sacc[nt][1]));
        mx1 = fmaxf(mx1, fmaxf(sacc[nt][2], sacc[nt][3]));
    }
    mx0 = fmaxf(mx0, __shfl_xor_sync(0xFFFFFFFFu, mx0, 1));
    mx0 = fmaxf(mx0, __shfl_xor_sync(0xFFFFFFFFu, mx0, 2));
    mx1 = fmaxf(mx1, __shfl_xor_sync(0xFFFFFFFFu, mx1, 1));
    mx1 = fmaxf(mx1, __shfl_xor_sync(0xFFFFFFFFu, mx1, 2));

    float sum0 = 0.f, sum1 = 0.f;
#pragma unroll
    for (int nt = 0; nt < 7; nt++) {
        sacc[nt][0] = __expf(sacc[nt][0] - mx0);
        sacc[nt][1] = __expf(sacc[nt][1] - mx0);
        sacc[nt][2] = __expf(sacc[nt][2] - mx1);
        sacc[nt][3] = __expf(sacc[nt][3] - mx1);
        sum0 += sacc[nt][0] + sacc[nt][1];
        sum1 += sacc[nt][2] + sacc[nt][3];
    }
    sum0 += __shfl_xor_sync(0xFFFFFFFFu, sum0, 1);
    sum0 += __shfl_xor_sync(0xFFFFFFFFu, sum0, 2);
    sum1 += __shfl_xor_sync(0xFFFFFFFFu, sum1, 1);
    sum1 += __shfl_xor_sync(0xFFFFFFFFu, sum1, 2);
    float inv0 = 1.f / sum0, inv1 = 1.f / sum1;
#pragma unroll
    for (int nt = 0; nt < 7; nt++) {
        sacc[nt][0] *= inv0; sacc[nt][1] *= inv0;
        sacc[nt][2] *= inv1; sacc[nt][3] *= inv1;
    }

    // ---- O = P V : re-fragment P via shuffles ----
    float o[4][4];
#pragma unroll
    for (int nt = 0; nt < 4; nt++)
#pragma unroll
        for (int r = 0; r < 4; r++) o[nt][r] = 0.f;

    int src0 = (lane & ~3) | (qid >> 1);
    int src1 = src0 + 2;
    bool odd = (qid & 1);

#pragma unroll
    for (int kt = 0; kt < 7; kt++) {
        float p00 = __shfl_sync(0xFFFFFFFFu, sacc[kt][0], src0);
        float p01 = __shfl_sync(0xFFFFFFFFu, sacc[kt][1], src0);
        float p10 = __shfl_sync(0xFFFFFFFFu, sacc[kt][0], src1);
        float p11 = __shfl_sync(0xFFFFFFFFu, sacc[kt][1], src1);
        float p20 = __shfl_sync(0xFFFFFFFFu, sacc[kt][2], src0);
        float p21 = __shfl_sync(0xFFFFFFFFu, sacc[kt][3], src0);
        float p30 = __shfl_sync(0xFFFFFFFFu, sacc[kt][2], src1);
        float p31 = __shfl_sync(0xFFFFFFFFu, sacc[kt][3], src1);
        unsigned a[4];
        a[0] = tf32u(odd ? p01 : p00);
        a[1] = tf32u(odd ? p21 : p20);
        a[2] = tf32u(odd ? p11 : p10);
        a[3] = tf32u(odd ? p31 : p30);
#pragma unroll
        for (int nt = 0; nt < 4; nt++) {
            float2 bv = *(const float2*)&vs[(kt * 4 + nt) * 68 + lane * 2];
            mma_tf32(o[nt], a, (const unsigned*)&bv);
        }
    }

    // ---- write ctx ----
    int r0 = m0 + gid, r1 = r0 + 8;
    float* op = g_ctx + ((size_t)w * NTOK) * CCH + h * HDIM;
#pragma unroll
    for (int nt = 0; nt < 4; nt++) {
        int d = nt * 8 + 2 * qid;
        if (r0 < NTOK) { float2 t = make_float2(o[nt][0], o[nt][1]); *(float2*)&op[r0 * CCH + d] = t; }
        if (r1 < NTOK) { float2 t = make_float2(o[nt][2], o[nt][3]); *(float2*)&op[r1 * CCH + d] = t; }
    }
}

// ---------------- launch ----------------
extern "C" void kernel_launch(void* const* d_in, const int* in_sizes, int n_in,
                              void* d_out, int out_size)
{
    const float* inputs = (const float*)d_in[0];
    const float* amask  = (const float*)d_in[1];
    const float* n1g    = (const float*)d_in[2];
    const float* n1b    = (const float*)d_in[3];
    const float* qkvw   = (const float*)d_in[4];
    const float* qkvb   = (const float*)d_in[5];
    const float* rpt    = (const float*)d_in[6];
    const int*   rpi    = (const int*)d_in[7];
    const float* pw     = (const float*)d_in[8];
    const float* pb     = (const float*)d_in[9];
    const float* lw     = (const float*)d_in[10];
    const float* lb     = (const float*)d_in[11];
    float* out = (float*)d_out;

    bias_kernel<<<(NHEAD * NTOK * NTOK + 255) / 256, 256>>>(rpt, rpi);
    ln_kernel<<<TOK / 8, 256>>>(inputs, n1g, n1b);
    gemm_kernel<0><<<dim3(9, TOK / 128), 256>>>(qkvw, qkvb, nullptr, nullptr);
    attn_kernel<<<dim3(BWIN, NHEAD), 128>>>(amask);
    gemm_kernel<1><<<dim3(3, TOK / 128), 256>>>(pw, pb, nullptr, nullptr);
    gemm_kernel<2><<<dim3(3, TOK / 128), 256>>>(lw, lb, inputs, out);
}